// round 15
// baseline (speedup 1.0000x reference)
#include <cuda_runtime.h>
#include <math.h>

// ---------------------------------------------------------------- constants
#define B_    32
#define T_    12
#define N_    200
#define H_    128
#define NB    6400            // B_*N_
#define NN    40000           // N_*N_
#define INV_SQRT_H 0.08838834764831845f   // 1/sqrt(128)

static __device__ __forceinline__ float sigmf_(float x){ return 1.0f/(1.0f+expf(-x)); }

// ---------------------------------------------------------------- scratch
// one big device-global buffer (no allocation allowed)
#define OFF_OUTS   0ULL                      // 12*6400*128
#define OFF_CUR    9830400ULL                // 12*6400*128
#define OFF_XM     19660800ULL               // 6400*1280
#define OFF_G      27852800ULL               // 6400*256
#define OFF_H0     29491200ULL               // 6400*128
#define OFF_H1     30310400ULL               // 6400*128
#define OFF_ATTN   31129600ULL               // 32*40000
#define OFF_ADJ    32409600ULL               // 32*40000
#define OFF_S1     33689600ULL               // 32*40000
#define OFF_S2     34969600ULL               // 32*40000
#define OFF_RS     36249600ULL               // 6400
#define OFF_CS     36256000ULL               // 6400
#define OFF_POOL   36262400ULL               // 6400*128
#define OFF_KEYM   37081600ULL               // 6400*64
#define OFF_QM     37491200ULL               // 6400*64
#define OFF_QMT    37900800ULL               // 32*64*200
#define OFF_LOG    38310400ULL               // 12*6400
#define OFF_XDEC   38387200ULL               // 6400
#define OFF_WHHT   38393600ULL               // 128*384
#define OFF_ATTWT  38442752ULL               // 128*64
#define OFF_WP     38450944ULL               // 1480320
#define TOTAL_F    39931264ULL

__device__ float g_buf[TOTAL_F];

// Wp sub-offsets (floats, relative to OFF_WP)
#define WPO_EG0 0
#define WPO_EC0 166400
#define WPO_EG1 249600
#define WPO_EC1 577280
#define WPO_DG0 741120
#define WPO_DC0 906240
#define WPO_DG1 988800
#define WPO_DC1 1316480

// ---------------------------------------------------------------- utility
__global__ void k_zero(float* p, int n){
    int i = blockIdx.x*256 + threadIdx.x;
    if (i < n) p[i] = 0.0f;
}

// AT[c*R + r] = A[r*C + c]
__global__ void k_transpose(const float* __restrict__ A, float* __restrict__ AT, int R, int C){
    int i = blockIdx.x*256 + threadIdx.x;
    if (i < R*C){ int r = i / C, c = i % C; AT[(size_t)c*R + r] = A[i]; }
}

// Wp[(m*C+c)*Nout + o] = W[(c*5+m)*Nout + o]
__global__ void k_reorder(const float* __restrict__ W, float* __restrict__ Wp, int C, int Nout){
    int i = blockIdx.x*256 + threadIdx.x;
    int tot = C*5*Nout;
    if (i < tot){
        int o = i % Nout; int rest = i / Nout;
        int m = rest / C; int c = rest % C;
        Wp[i] = W[((size_t)c*5 + m)*Nout + o];
    }
}

// qmT[(b*64+d)*200+m] = qm[(b*200+m)*64+d]
__global__ void k_qmT(const float* __restrict__ qm, float* __restrict__ qmT){
    int i = blockIdx.x*256 + threadIdx.x;
    if (i < B_*N_*64){
        int d = i % 64; int rest = i / 64; int m = rest % N_, b = rest / N_;
        qmT[((size_t)b*64 + d)*N_ + m] = qm[i];
    }
}

// ---------------------------------------------------------------- GRU (supports)
// rows = n*B_ + b; each block owns 8 consecutive rows for all 12 timesteps.
__global__ void k_gru(const float* __restrict__ ein, const float* __restrict__ Wih,
                      const float* __restrict__ WhhT, const float* __restrict__ bih,
                      const float* __restrict__ bhh, float* __restrict__ outs){
    int tid = threadIdx.x;           // 128
    int r0  = blockIdx.x * 8;
    __shared__ float hs[8][128];
    #pragma unroll
    for (int rr = 0; rr < 8; rr++) hs[rr][tid] = 0.0f;

    float wi00 = Wih[tid*2],         wi01 = Wih[tid*2+1];
    float wi10 = Wih[(128+tid)*2],   wi11 = Wih[(128+tid)*2+1];
    float wi20 = Wih[(256+tid)*2],   wi21 = Wih[(256+tid)*2+1];
    float bi0 = bih[tid], bi1 = bih[128+tid], bi2 = bih[256+tid];
    float bh0 = bhh[tid], bh1 = bhh[128+tid], bh2 = bhh[256+tid];
    __syncthreads();

    for (int t = 0; t < T_; t++){
        float a0[8], a1[8], a2[8];
        #pragma unroll
        for (int rr = 0; rr < 8; rr++){ a0[rr]=0.f; a1[rr]=0.f; a2[rr]=0.f; }
        for (int k = 0; k < 128; k++){
            float w0 = WhhT[k*384 + tid];
            float w1 = WhhT[k*384 + 128 + tid];
            float w2 = WhhT[k*384 + 256 + tid];
            #pragma unroll
            for (int rr = 0; rr < 8; rr++){
                float hk = hs[rr][k];
                a0[rr] += w0*hk; a1[rr] += w1*hk; a2[rr] += w2*hk;
            }
        }
        __syncthreads();
        #pragma unroll
        for (int rr = 0; rr < 8; rr++){
            int row = r0 + rr;
            int b = row & 31, n = row >> 5;      // row = n*B_ + b
            size_t xi = (((size_t)b*T_ + t)*N_ + n)*2;
            float x0 = ein[xi], x1 = ein[xi+1];
            float ir = x0*wi00 + x1*wi01 + bi0;
            float iz = x0*wi10 + x1*wi11 + bi1;
            float ig = x0*wi20 + x1*wi21 + bi2;
            float hprev = hs[rr][tid];
            float rg = sigmf_(ir + a0[rr] + bh0);
            float zg = sigmf_(iz + a1[rr] + bh1);
            float ng = tanhf(ig + rg*(a2[rr] + bh2));
            float hn = (1.0f - zg)*ng + zg*hprev;
            hs[rr][tid] = hn;
            outs[((size_t)t*NB + row)*128 + tid] = hn;
        }
        __syncthreads();
    }
}

// logits[t*NB+row] = sum_d relu(outs[t,row,:]·attW[d,:] + attb[d]) * wlen[d]
__global__ void k_attlogits(const float* __restrict__ outs, const float* __restrict__ attWT,
                            const float* __restrict__ attb, const float* __restrict__ wlen,
                            float* __restrict__ logits){
    int row = blockIdx.x;
    int d = threadIdx.x;             // 64
    __shared__ float ho[128];
    __shared__ float red[64];
    float bd = attb[d], wd = wlen[d];
    for (int t = 0; t < T_; t++){
        ho[d]      = outs[((size_t)t*NB + row)*128 + d];
        ho[d + 64] = outs[((size_t)t*NB + row)*128 + d + 64];
        __syncthreads();
        float acc = 0.f;
        #pragma unroll 4
        for (int hh = 0; hh < 128; hh++) acc += ho[hh]*attWT[hh*64 + d];
        float sc = fmaxf(acc + bd, 0.f) * wd;
        red[d] = sc; __syncthreads();
        for (int off = 32; off > 0; off >>= 1){
            if (d < off) red[d] += red[d + off];
            __syncthreads();
        }
        if (d == 0) logits[t*NB + row] = red[0];
        __syncthreads();
    }
}

// softmax over t, pooled[b*N+n, h]; GRU row = n*B+b
__global__ void k_pool(const float* __restrict__ outs, const float* __restrict__ logits,
                       float* __restrict__ pooled){
    int row = blockIdx.x, tid = threadIdx.x;   // 128
    __shared__ float w[12];
    if (tid < 12) w[tid] = logits[tid*NB + row];
    __syncthreads();
    if (tid == 0){
        float mx = w[0];
        for (int t = 1; t < 12; t++) mx = fmaxf(mx, w[t]);
        float s = 0.f;
        for (int t = 0; t < 12; t++){ w[t] = expf(w[t]-mx); s += w[t]; }
        float inv = 1.0f/s;
        for (int t = 0; t < 12; t++) w[t] *= inv;
    }
    __syncthreads();
    float acc = 0.f;
    #pragma unroll
    for (int t = 0; t < 12; t++) acc += w[t]*outs[((size_t)t*NB + row)*128 + tid];
    int b = row & 31, n = row >> 5;
    pooled[((size_t)b*N_ + n)*128 + tid] = acc;
}

// attn row softmax: attn[b,n,m] = softmax_m( keym[b,n]·qm[b,m] / sqrt(H) )
__global__ void k_attn(const float* __restrict__ keym, const float* __restrict__ qmT,
                       float* __restrict__ attn){
    int bn = blockIdx.x; int b = bn / N_;
    int tid = threadIdx.x;           // 256
    __shared__ float keys[64];
    __shared__ float vals[256];
    __shared__ float red[256];
    if (tid < 64) keys[tid] = keym[(size_t)bn*64 + tid];
    __syncthreads();
    float v = -1e30f;
    if (tid < N_){
        float acc = 0.f;
        const float* q = qmT + (size_t)b*64*N_;
        #pragma unroll 4
        for (int d = 0; d < 64; d++) acc += keys[d]*q[d*N_ + tid];
        v = acc * INV_SQRT_H;
    }
    vals[tid] = v; red[tid] = v;
    __syncthreads();
    for (int off = 128; off > 0; off >>= 1){
        if (tid < off) red[tid] = fmaxf(red[tid], red[tid+off]);
        __syncthreads();
    }
    float mx = red[0];
    __syncthreads();
    float e = (tid < N_) ? expf(vals[tid]-mx) : 0.f;
    red[tid] = e;
    __syncthreads();
    for (int off = 128; off > 0; off >>= 1){
        if (tid < off) red[tid] += red[tid+off];
        __syncthreads();
    }
    float inv = 1.0f/red[0];
    if (tid < N_) attn[(size_t)b*NN + (bn % N_)*N_ + tid] = e*inv;
}

// top-k threshold + adj (+eye) + rowsum
__global__ void k_topk(const float* __restrict__ attn, float* __restrict__ adj,
                       float* __restrict__ rowsum, const int* __restrict__ topk){
    int bn = blockIdx.x; int b = bn / N_, n = bn % N_;
    int tid = threadIdx.x;           // 256
    __shared__ float vals[200];
    __shared__ float red[256];
    if (tid < N_) vals[tid] = attn[(size_t)b*NN + n*N_ + tid];
    __syncthreads();
    int kk = *topk;
    float cand = -1e30f;
    if (tid < N_){
        float v = vals[tid]; int cnt = 0;
        for (int j = 0; j < N_; j++) cnt += (vals[j] >= v) ? 1 : 0;
        if (cnt >= kk) cand = v;
    }
    red[tid] = cand;
    __syncthreads();
    for (int off = 128; off > 0; off >>= 1){
        if (tid < off) red[tid] = fmaxf(red[tid], red[tid+off]);
        __syncthreads();
    }
    float kth = red[0];
    __syncthreads();
    float a = 0.f;
    if (tid < N_){
        float v = vals[tid];
        a = ((v >= kth) ? v : 0.f) + ((tid == n) ? 1.0f : 0.f);
        adj[(size_t)b*NN + n*N_ + tid] = a;
    }
    red[tid] = (tid < N_) ? a : 0.f;
    __syncthreads();
    for (int off = 128; off > 0; off >>= 1){
        if (tid < off) red[tid] += red[tid+off];
        __syncthreads();
    }
    if (tid == 0) rowsum[bn] = red[0];
}

__global__ void k_colsum(const float* __restrict__ adj, float* __restrict__ colsum){
    int b = blockIdx.x; int m = threadIdx.x;     // 256
    if (m < N_){
        float s = 0.f;
        for (int i = 0; i < N_; i++) s += adj[(size_t)b*NN + i*N_ + m];
        colsum[b*N_ + m] = s;
    }
}

// s1[b,i,j] = adj[b,j,i]/rowsum[b,j]; s2[b,i,j] = adj[b,i,j]/colsum[b,j]
__global__ void k_builds(const float* __restrict__ adj, const float* __restrict__ rowsum,
                         const float* __restrict__ colsum,
                         float* __restrict__ s1, float* __restrict__ s2){
    int idx = blockIdx.x*256 + threadIdx.x;
    if (idx < B_*NN){
        int b = idx / NN; int r = idx % NN; int i = r / N_, j = r % N_;
        float rs = rowsum[b*N_ + j]; float rinv = (rs == 0.f) ? 0.f : 1.0f/rs;
        float cs = colsum[b*N_ + j]; float cinv = (cs == 0.f) ? 0.f : 1.0f/cs;
        s1[idx] = adj[(size_t)b*NN + j*N_ + i]*rinv;
        s2[idx] = adj[idx]*cinv;
    }
}

// ---------------------------------------------------------------- cell kernels
// slot-0 concat: XM[row, c] = c<xC ? x : h (optionally * r-gate)
__global__ void k_concat(const float* __restrict__ xsrc, int xC, int isEnc, int t,
                         const float* __restrict__ h, const float* __restrict__ rg,
                         float* __restrict__ XM, int ld){
    int idx = blockIdx.x*256 + threadIdx.x;
    int C = xC + 128;
    if (idx < NB*C){
        int row = idx / C, c = idx % C;
        float v;
        if (c < xC){
            if (isEnc){
                int b = row / N_, n = row % N_;
                v = xsrc[(((size_t)b*T_ + t)*N_ + n)*2 + c];
            } else {
                v = xsrc[(size_t)row*xC + c];
            }
        } else {
            int hc = c - xC;
            v = h[(size_t)row*128 + hc];
            if (rg) v *= rg[(size_t)row*256 + hc];
        }
        XM[(size_t)row*ld + c] = v;
    }
}

// out[b,i,cOut] = alpha * sum_j S[b,i,j]*XM[b,j,cIn] + beta*XM[b,i,cBeta]
__global__ void k_bmm(const float* __restrict__ S, float* __restrict__ XM, int ld,
                      int inOff, int outOff, int betaOff, float alpha, float beta, int C){
    __shared__ float Ss[32][33];
    __shared__ float Xs[32][33];
    int b = blockIdx.z;
    int i0 = blockIdx.y*32, c0 = blockIdx.x*32;
    int tx = threadIdx.x, ty = threadIdx.y;   // (32,8)
    int tid = ty*32 + tx;
    const float* Sb = S + (size_t)b*NN;
    float acc[4] = {0.f,0.f,0.f,0.f};
    for (int j0 = 0; j0 < N_; j0 += 32){
        #pragma unroll
        for (int e = 0; e < 4; e++){
            int idx = e*256 + tid; int r = idx >> 5, cc = idx & 31;
            Ss[r][cc] = (i0+r < N_ && j0+cc < N_) ? Sb[(i0+r)*N_ + j0+cc] : 0.f;
            Xs[r][cc] = (j0+r < N_ && c0+cc < C)
                      ? XM[((size_t)b*N_ + j0+r)*ld + inOff + c0+cc] : 0.f;
        }
        __syncthreads();
        #pragma unroll
        for (int jj = 0; jj < 32; jj++){
            float xv = Xs[jj][tx];
            #pragma unroll
            for (int r = 0; r < 4; r++) acc[r] += Ss[ty + 8*r][jj]*xv;
        }
        __syncthreads();
    }
    int c = c0 + tx;
    if (c < C){
        #pragma unroll
        for (int r = 0; r < 4; r++){
            int i = i0 + ty + 8*r;
            if (i < N_){
                size_t base = ((size_t)b*N_ + i)*ld;
                float v = alpha*acc[r];
                if (beta != 0.f) v += beta*XM[base + betaOff + c];
                XM[base + outOff + c] = v;
            }
        }
    }
}

// GEMM: C[rows, Nout] = A[rows, K] @ B[K, Nout] (+bias) with fused epilogues
// mode 0: plain;  mode 1: sigmoid -> G;  mode 2: tanh + GRU update (h in-place)
__global__ void k_gemm(const float* __restrict__ A, int lda,
                       const float* __restrict__ Bm,
                       const float* __restrict__ bias,
                       float* __restrict__ Cout,
                       int K, int Nout, int mode,
                       const float* __restrict__ G,
                       const float* __restrict__ h,
                       float* __restrict__ hout2){
    __shared__ float As[16][64];
    __shared__ float Bs[16][65];
    int tx = threadIdx.x, ty = threadIdx.y;   // (16,16)
    int tid = ty*16 + tx;
    int i0 = blockIdx.y*64, j0 = blockIdx.x*64;
    float acc[4][4];
    #pragma unroll
    for (int r = 0; r < 4; r++)
        #pragma unroll
        for (int s = 0; s < 4; s++) acc[r][s] = 0.f;

    for (int kt = 0; kt < K; kt += 16){
        #pragma unroll
        for (int e = 0; e < 4; e++){
            int idx = tid*4 + e;
            int i = idx >> 4, kk = idx & 15;
            As[kk][i] = (kt+kk < K) ? A[(size_t)(i0+i)*lda + kt+kk] : 0.f;
        }
        #pragma unroll
        for (int e = 0; e < 4; e++){
            int idx = e*256 + tid;
            int kk = idx >> 6, j = idx & 63;
            Bs[kk][j] = (kt+kk < K) ? Bm[(size_t)(kt+kk)*Nout + j0 + j] : 0.f;
        }
        __syncthreads();
        #pragma unroll
        for (int kk = 0; kk < 16; kk++){
            float a[4], bb[4];
            #pragma unroll
            for (int r = 0; r < 4; r++) a[r] = As[kk][ty + 16*r];
            #pragma unroll
            for (int s = 0; s < 4; s++) bb[s] = Bs[kk][tx + 16*s];
            #pragma unroll
            for (int r = 0; r < 4; r++)
                #pragma unroll
                for (int s = 0; s < 4; s++) acc[r][s] += a[r]*bb[s];
        }
        __syncthreads();
    }
    #pragma unroll
    for (int r = 0; r < 4; r++){
        int row = i0 + ty + 16*r;
        #pragma unroll
        for (int s = 0; s < 4; s++){
            int col = j0 + tx + 16*s;
            float v = acc[r][s] + (bias ? bias[col] : 0.f);
            if (mode == 0){
                Cout[(size_t)row*Nout + col] = v;
            } else if (mode == 1){
                Cout[(size_t)row*Nout + col] = sigmf_(v);
            } else {
                float c = tanhf(v);
                float u = G[(size_t)row*256 + 128 + col];
                float hn = u*h[(size_t)row*128 + col] + (1.0f - u)*c;
                Cout[(size_t)row*128 + col] = hn;
                if (hout2) hout2[(size_t)row*128 + col] = hn;
            }
        }
    }
}

// proj: out[t,b,n] = h1[row]·projW + projb; also next decoder input
__global__ void k_proj(const float* __restrict__ h1, const float* __restrict__ projW,
                       const float* __restrict__ projb, float* __restrict__ out,
                       float* __restrict__ xdec, int t){
    int row = blockIdx.x; int tid = threadIdx.x;   // 128
    __shared__ float red[128];
    red[tid] = h1[(size_t)row*128 + tid]*projW[tid];
    __syncthreads();
    for (int off = 64; off > 0; off >>= 1){
        if (tid < off) red[tid] += red[tid+off];
        __syncthreads();
    }
    if (tid == 0){
        float v = red[0] + projb[0];
        int b = row / N_, n = row % N_;
        out[((size_t)t*B_ + b)*N_ + n] = v;
        xdec[row] = v;
    }
}

// ---------------------------------------------------------------- host
extern "C" void kernel_launch(void* const* d_in, const int* in_sizes, int n_in,
                              void* d_out, int out_size){
    (void)in_sizes; (void)n_in; (void)out_size;
    float* base = nullptr;
    cudaGetSymbolAddress((void**)&base, g_buf);

    float* outs   = base + OFF_OUTS;
    float* cur    = base + OFF_CUR;
    float* XM     = base + OFF_XM;
    float* G      = base + OFF_G;
    float* h0     = base + OFF_H0;
    float* h1     = base + OFF_H1;
    float* attn   = base + OFF_ATTN;
    float* adj    = base + OFF_ADJ;
    float* s1     = base + OFF_S1;
    float* s2     = base + OFF_S2;
    float* rowsum = base + OFF_RS;
    float* colsum = base + OFF_CS;
    float* pooled = base + OFF_POOL;
    float* keym   = base + OFF_KEYM;
    float* qm     = base + OFF_QM;
    float* qmT    = base + OFF_QMT;
    float* logits = base + OFF_LOG;
    float* xdec   = base + OFF_XDEC;
    float* whhT   = base + OFF_WHHT;
    float* attWT  = base + OFF_ATTWT;
    float* Wp     = base + OFF_WP;

    const float* ein     = (const float*)d_in[0];
    const float* gru_Wih = (const float*)d_in[2];
    const float* gru_Whh = (const float*)d_in[3];
    const float* gru_bih = (const float*)d_in[4];
    const float* gru_bhh = (const float*)d_in[5];
    const float* att_W   = (const float*)d_in[6];
    const float* att_b   = (const float*)d_in[7];
    const float* w_len_C = (const float*)d_in[8];
    const float* w_key   = (const float*)d_in[9];
    const float* w_query = (const float*)d_in[10];
    const float* enc_Wg0 = (const float*)d_in[11];
    const float* enc_bg0 = (const float*)d_in[12];
    const float* enc_Wc0 = (const float*)d_in[13];
    const float* enc_bc0 = (const float*)d_in[14];
    const float* enc_Wg1 = (const float*)d_in[15];
    const float* enc_bg1 = (const float*)d_in[16];
    const float* enc_Wc1 = (const float*)d_in[17];
    const float* enc_bc1 = (const float*)d_in[18];
    const float* dec_Wg0 = (const float*)d_in[19];
    const float* dec_bg0 = (const float*)d_in[20];
    const float* dec_Wc0 = (const float*)d_in[21];
    const float* dec_bc0 = (const float*)d_in[22];
    const float* dec_Wg1 = (const float*)d_in[23];
    const float* dec_bg1 = (const float*)d_in[24];
    const float* dec_Wc1 = (const float*)d_in[25];
    const float* dec_bc1 = (const float*)d_in[26];
    const float* proj_W  = (const float*)d_in[27];
    const float* proj_b  = (const float*)d_in[28];
    const int*   topk    = (const int*)d_in[29];
    float* out = (float*)d_out;

    dim3 gblk(16,16);

    // ---- prep: transposes & weight reorders
    k_transpose<<<(384*128+255)/256,256>>>(gru_Whh, whhT, 384, 128);
    k_transpose<<<(64*128+255)/256,256>>>(att_W, attWT, 64, 128);
    struct RW { const float* W; int off; int C; int Nout; };
    RW rws[8] = {
        {enc_Wg0, WPO_EG0, 130, 256}, {enc_Wc0, WPO_EC0, 130, 128},
        {enc_Wg1, WPO_EG1, 256, 256}, {enc_Wc1, WPO_EC1, 256, 128},
        {dec_Wg0, WPO_DG0, 129, 256}, {dec_Wc0, WPO_DC0, 129, 128},
        {dec_Wg1, WPO_DG1, 256, 256}, {dec_Wc1, WPO_DC1, 256, 128},
    };
    for (int i = 0; i < 8; i++){
        int tot = rws[i].C*5*rws[i].Nout;
        k_reorder<<<(tot+255)/256,256>>>(rws[i].W, Wp + rws[i].off, rws[i].C, rws[i].Nout);
    }

    // ---- zero initial states
    k_zero<<<(NB*128+255)/256,256>>>(h0, NB*128);
    k_zero<<<(NB*128+255)/256,256>>>(h1, NB*128);
    k_zero<<<(NB+255)/256,256>>>(xdec, NB);

    // ---- supports
    k_gru<<<NB/8,128>>>(ein, gru_Wih, whhT, gru_bih, gru_bhh, outs);
    k_attlogits<<<NB,64>>>(outs, attWT, att_b, w_len_C, logits);
    k_pool<<<NB,128>>>(outs, logits, pooled);
    k_gemm<<<dim3(1,100),gblk>>>(pooled,128, w_key,   nullptr, keym, 128, 64, 0, nullptr, nullptr, nullptr);
    k_gemm<<<dim3(1,100),gblk>>>(pooled,128, w_query, nullptr, qm,   128, 64, 0, nullptr, nullptr, nullptr);
    k_qmT<<<(B_*N_*64+255)/256,256>>>(qm, qmT);
    k_attn<<<NB,256>>>(keym, qmT, attn);
    k_topk<<<NB,256>>>(attn, adj, rowsum, topk);
    k_colsum<<<B_,256>>>(adj, colsum);
    k_builds<<<(B_*NN+255)/256,256>>>(adj, rowsum, colsum, s1, s2);

    // ---- one DCGRU cell
    auto cell = [&](const float* xsrc, int xC, int isEnc, int t, float* h,
                    const float* Wg, const float* bg,
                    const float* Wc, const float* bc, float* hout2){
        int C = xC + 128, ld = 5*C, K = 5*C;
        dim3 bgrd((C+31)/32, 7, 32), bblk(32,8);
        // gate gconv
        k_concat<<<(NB*C+255)/256,256>>>(xsrc, xC, isEnc, t, h, nullptr, XM, ld);
        k_bmm<<<bgrd,bblk>>>(s1, XM, ld, 0,   C,   0, 1.f,  0.f, C);
        k_bmm<<<bgrd,bblk>>>(s1, XM, ld, C,   2*C, 0, 2.f, -1.f, C);
        k_bmm<<<bgrd,bblk>>>(s2, XM, ld, 0,   3*C, 0, 1.f,  0.f, C);
        k_bmm<<<bgrd,bblk>>>(s2, XM, ld, 3*C, 4*C, 0, 2.f, -1.f, C);
        k_gemm<<<dim3(4,100),gblk>>>(XM, ld, Wg, bg, G, K, 256, 1, nullptr, nullptr, nullptr);
        // candidate gconv (input = concat(x, r*h))
        k_concat<<<(NB*C+255)/256,256>>>(xsrc, xC, isEnc, t, h, G, XM, ld);
        k_bmm<<<bgrd,bblk>>>(s1, XM, ld, 0,   C,   0, 1.f,  0.f, C);
        k_bmm<<<bgrd,bblk>>>(s1, XM, ld, C,   2*C, 0, 2.f, -1.f, C);
        k_bmm<<<bgrd,bblk>>>(s2, XM, ld, 0,   3*C, 0, 1.f,  0.f, C);
        k_bmm<<<bgrd,bblk>>>(s2, XM, ld, 3*C, 4*C, 0, 2.f, -1.f, C);
        k_gemm<<<dim3(2,100),gblk>>>(XM, ld, Wc, bc, h, K, 128, 2, G, h, hout2);
    };

    // ---- encoder
    for (int t = 0; t < T_; t++)
        cell(ein, 2, 1, t, h0, Wp+WPO_EG0, enc_bg0, Wp+WPO_EC0, enc_bc0,
             cur + (size_t)t*NB*128);
    for (int t = 0; t < T_; t++)
        cell(cur + (size_t)t*NB*128, 128, 0, 0, h1, Wp+WPO_EG1, enc_bg1,
             Wp+WPO_EC1, enc_bc1, nullptr);

    // ---- decoder (autoregressive)
    for (int t = 0; t < T_; t++){
        cell(xdec, 1, 0, 0, h0, Wp+WPO_DG0, dec_bg0, Wp+WPO_DC0, dec_bc0, nullptr);
        cell(h0, 128, 0, 0, h1, Wp+WPO_DG1, dec_bg1, Wp+WPO_DC1, dec_bc1, nullptr);
        k_proj<<<NB,128>>>(h1, proj_W, proj_b, out, xdec, t);
    }
}

// round 16
// speedup vs baseline: 1.8462x; 1.8462x over previous
#include <cuda_runtime.h>
#include <math.h>

// ---------------------------------------------------------------- constants
#define B_    32
#define T_    12
#define N_    200
#define H_    128
#define NB    6400            // B_*N_
#define NN    40000           // N_*N_
#define INV_SQRT_H 0.08838834764831845f   // 1/sqrt(128)

static __device__ __forceinline__ float sigmf_(float x){ return 1.0f/(1.0f+expf(-x)); }

// ---------------------------------------------------------------- scratch
#define OFF_OUTS   0ULL                      // 12*6400*128
#define OFF_CUR    9830400ULL                // 12*6400*128
#define OFF_XM     19660800ULL               // 6400*1280
#define OFF_G      27852800ULL               // 6400*256
#define OFF_H0     29491200ULL               // 6400*128
#define OFF_H1     30310400ULL               // 6400*128
#define OFF_ATTN   31129600ULL               // 32*40000
#define OFF_ADJ    32409600ULL               // 32*40000
#define OFF_RS     36249600ULL               // 6400
#define OFF_CS     36256000ULL               // 6400
#define OFF_POOL   36262400ULL               // 6400*128
#define OFF_KEYM   37081600ULL               // 6400*64
#define OFF_QM     37491200ULL               // 6400*64
#define OFF_QMT    37900800ULL               // 32*64*200
#define OFF_LOG    38310400ULL               // 12*6400
#define OFF_XDEC   38387200ULL               // 6400
#define OFF_WHHT   38393600ULL               // 128*384
#define OFF_ATTWT  38442752ULL               // 128*64
#define OFF_WP     38450944ULL               // 1480320
#define TOTAL_F    39931264ULL

__device__ float g_buf[TOTAL_F];

// ELL sparse supports: z in {0:s1, 1:s2}, per row up to N_ entries
__device__ int   g_eidx[2*NB*N_];
__device__ float g_eval[2*NB*N_];
__device__ int   g_ecnt[2*NB];

// Wp sub-offsets (floats, relative to OFF_WP)
#define WPO_EG0 0
#define WPO_EC0 166400
#define WPO_EG1 249600
#define WPO_EC1 577280
#define WPO_DG0 741120
#define WPO_DC0 906240
#define WPO_DG1 988800
#define WPO_DC1 1316480

// ---------------------------------------------------------------- utility
__global__ void k_zero(float* p, int n){
    int i = blockIdx.x*256 + threadIdx.x;
    if (i < n) p[i] = 0.0f;
}

__global__ void k_transpose(const float* __restrict__ A, float* __restrict__ AT, int R, int C){
    int i = blockIdx.x*256 + threadIdx.x;
    if (i < R*C){ int r = i / C, c = i % C; AT[(size_t)c*R + r] = A[i]; }
}

// Wp[(m*C+c)*Nout + o] = W[(c*5+m)*Nout + o]
__global__ void k_reorder(const float* __restrict__ W, float* __restrict__ Wp, int C, int Nout){
    int i = blockIdx.x*256 + threadIdx.x;
    int tot = C*5*Nout;
    if (i < tot){
        int o = i % Nout; int rest = i / Nout;
        int m = rest / C; int c = rest % C;
        Wp[i] = W[((size_t)c*5 + m)*Nout + o];
    }
}

__global__ void k_qmT(const float* __restrict__ qm, float* __restrict__ qmT){
    int i = blockIdx.x*256 + threadIdx.x;
    if (i < B_*N_*64){
        int d = i % 64; int rest = i / 64; int m = rest % N_, b = rest / N_;
        qmT[((size_t)b*64 + d)*N_ + m] = qm[i];
    }
}

// ---------------------------------------------------------------- GRU (supports)
__global__ void k_gru(const float* __restrict__ ein, const float* __restrict__ Wih,
                      const float* __restrict__ WhhT, const float* __restrict__ bih,
                      const float* __restrict__ bhh, float* __restrict__ outs){
    int tid = threadIdx.x;           // 128
    int r0  = blockIdx.x * 8;
    __shared__ float hs[8][128];
    #pragma unroll
    for (int rr = 0; rr < 8; rr++) hs[rr][tid] = 0.0f;

    float wi00 = Wih[tid*2],         wi01 = Wih[tid*2+1];
    float wi10 = Wih[(128+tid)*2],   wi11 = Wih[(128+tid)*2+1];
    float wi20 = Wih[(256+tid)*2],   wi21 = Wih[(256+tid)*2+1];
    float bi0 = bih[tid], bi1 = bih[128+tid], bi2 = bih[256+tid];
    float bh0 = bhh[tid], bh1 = bhh[128+tid], bh2 = bhh[256+tid];
    __syncthreads();

    for (int t = 0; t < T_; t++){
        float a0[8], a1[8], a2[8];
        #pragma unroll
        for (int rr = 0; rr < 8; rr++){ a0[rr]=0.f; a1[rr]=0.f; a2[rr]=0.f; }
        for (int k = 0; k < 128; k++){
            float w0 = WhhT[k*384 + tid];
            float w1 = WhhT[k*384 + 128 + tid];
            float w2 = WhhT[k*384 + 256 + tid];
            #pragma unroll
            for (int rr = 0; rr < 8; rr++){
                float hk = hs[rr][k];
                a0[rr] += w0*hk; a1[rr] += w1*hk; a2[rr] += w2*hk;
            }
        }
        __syncthreads();
        #pragma unroll
        for (int rr = 0; rr < 8; rr++){
            int row = r0 + rr;
            int b = row & 31, n = row >> 5;      // row = n*B_ + b
            size_t xi = (((size_t)b*T_ + t)*N_ + n)*2;
            float x0 = ein[xi], x1 = ein[xi+1];
            float ir = x0*wi00 + x1*wi01 + bi0;
            float iz = x0*wi10 + x1*wi11 + bi1;
            float ig = x0*wi20 + x1*wi21 + bi2;
            float hprev = hs[rr][tid];
            float rg = sigmf_(ir + a0[rr] + bh0);
            float zg = sigmf_(iz + a1[rr] + bh1);
            float ng = tanhf(ig + rg*(a2[rr] + bh2));
            float hn = (1.0f - zg)*ng + zg*hprev;
            hs[rr][tid] = hn;
            outs[((size_t)t*NB + row)*128 + tid] = hn;
        }
        __syncthreads();
    }
}

__global__ void k_attlogits(const float* __restrict__ outs, const float* __restrict__ attWT,
                            const float* __restrict__ attb, const float* __restrict__ wlen,
                            float* __restrict__ logits){
    int row = blockIdx.x;
    int d = threadIdx.x;             // 64
    __shared__ float ho[128];
    __shared__ float red[64];
    float bd = attb[d], wd = wlen[d];
    for (int t = 0; t < T_; t++){
        ho[d]      = outs[((size_t)t*NB + row)*128 + d];
        ho[d + 64] = outs[((size_t)t*NB + row)*128 + d + 64];
        __syncthreads();
        float acc = 0.f;
        #pragma unroll 4
        for (int hh = 0; hh < 128; hh++) acc += ho[hh]*attWT[hh*64 + d];
        float sc = fmaxf(acc + bd, 0.f) * wd;
        red[d] = sc; __syncthreads();
        for (int off = 32; off > 0; off >>= 1){
            if (d < off) red[d] += red[d + off];
            __syncthreads();
        }
        if (d == 0) logits[t*NB + row] = red[0];
        __syncthreads();
    }
}

__global__ void k_pool(const float* __restrict__ outs, const float* __restrict__ logits,
                       float* __restrict__ pooled){
    int row = blockIdx.x, tid = threadIdx.x;   // 128
    __shared__ float w[12];
    if (tid < 12) w[tid] = logits[tid*NB + row];
    __syncthreads();
    if (tid == 0){
        float mx = w[0];
        for (int t = 1; t < 12; t++) mx = fmaxf(mx, w[t]);
        float s = 0.f;
        for (int t = 0; t < 12; t++){ w[t] = expf(w[t]-mx); s += w[t]; }
        float inv = 1.0f/s;
        for (int t = 0; t < 12; t++) w[t] *= inv;
    }
    __syncthreads();
    float acc = 0.f;
    #pragma unroll
    for (int t = 0; t < 12; t++) acc += w[t]*outs[((size_t)t*NB + row)*128 + tid];
    int b = row & 31, n = row >> 5;
    pooled[((size_t)b*N_ + n)*128 + tid] = acc;
}

__global__ void k_attn(const float* __restrict__ keym, const float* __restrict__ qmT,
                       float* __restrict__ attn){
    int bn = blockIdx.x; int b = bn / N_;
    int tid = threadIdx.x;           // 256
    __shared__ float keys[64];
    __shared__ float vals[256];
    __shared__ float red[256];
    if (tid < 64) keys[tid] = keym[(size_t)bn*64 + tid];
    __syncthreads();
    float v = -1e30f;
    if (tid < N_){
        float acc = 0.f;
        const float* q = qmT + (size_t)b*64*N_;
        #pragma unroll 4
        for (int d = 0; d < 64; d++) acc += keys[d]*q[d*N_ + tid];
        v = acc * INV_SQRT_H;
    }
    vals[tid] = v; red[tid] = v;
    __syncthreads();
    for (int off = 128; off > 0; off >>= 1){
        if (tid < off) red[tid] = fmaxf(red[tid], red[tid+off]);
        __syncthreads();
    }
    float mx = red[0];
    __syncthreads();
    float e = (tid < N_) ? expf(vals[tid]-mx) : 0.f;
    red[tid] = e;
    __syncthreads();
    for (int off = 128; off > 0; off >>= 1){
        if (tid < off) red[tid] += red[tid+off];
        __syncthreads();
    }
    float inv = 1.0f/red[0];
    if (tid < N_) attn[(size_t)b*NN + (bn % N_)*N_ + tid] = e*inv;
}

__global__ void k_topk(const float* __restrict__ attn, float* __restrict__ adj,
                       float* __restrict__ rowsum, const int* __restrict__ topk){
    int bn = blockIdx.x; int b = bn / N_, n = bn % N_;
    int tid = threadIdx.x;           // 256
    __shared__ float vals[200];
    __shared__ float red[256];
    if (tid < N_) vals[tid] = attn[(size_t)b*NN + n*N_ + tid];
    __syncthreads();
    int kk = *topk;
    float cand = -1e30f;
    if (tid < N_){
        float v = vals[tid]; int cnt = 0;
        for (int j = 0; j < N_; j++) cnt += (vals[j] >= v) ? 1 : 0;
        if (cnt >= kk) cand = v;
    }
    red[tid] = cand;
    __syncthreads();
    for (int off = 128; off > 0; off >>= 1){
        if (tid < off) red[tid] = fmaxf(red[tid], red[tid+off]);
        __syncthreads();
    }
    float kth = red[0];
    __syncthreads();
    float a = 0.f;
    if (tid < N_){
        float v = vals[tid];
        a = ((v >= kth) ? v : 0.f) + ((tid == n) ? 1.0f : 0.f);
        adj[(size_t)b*NN + n*N_ + tid] = a;
    }
    red[tid] = (tid < N_) ? a : 0.f;
    __syncthreads();
    for (int off = 128; off > 0; off >>= 1){
        if (tid < off) red[tid] += red[tid+off];
        __syncthreads();
    }
    if (tid == 0) rowsum[bn] = red[0];
}

__global__ void k_colsum(const float* __restrict__ adj, float* __restrict__ colsum){
    int b = blockIdx.x; int m = threadIdx.x;     // 256
    if (m < N_){
        float s = 0.f;
        for (int i = 0; i < N_; i++) s += adj[(size_t)b*NN + i*N_ + m];
        colsum[b*N_ + m] = s;
    }
}

// ---------------------------------------------------------------- ELL build
// s1[b,i,j] = adj[b,j,i]/rowsum[b,j]; s2[b,i,j] = adj[b,i,j]/colsum[b,j]
// One warp per (z,row); ballot-ordered compaction => deterministic order.
__global__ void k_ell(const float* __restrict__ adj, const float* __restrict__ rowsum,
                      const float* __restrict__ colsum,
                      int* __restrict__ eidx, float* __restrict__ eval,
                      int* __restrict__ ecnt){
    int gw = (blockIdx.x*blockDim.x + threadIdx.x) >> 5;
    int lane = threadIdx.x & 31;
    if (gw >= 2*NB) return;
    int z = gw / NB; int row = gw % NB; int b = row / N_, i = row % N_;
    int cnt = 0;
    size_t base = (size_t)gw * N_;
    for (int j0 = 0; j0 < N_; j0 += 32){
        int j = j0 + lane;
        float v = 0.f;
        if (j < N_)
            v = (z == 0) ? adj[(size_t)b*NN + j*N_ + i]
                         : adj[(size_t)b*NN + i*N_ + j];
        bool nz = (v != 0.f);
        unsigned m = __ballot_sync(0xffffffffu, nz);
        if (nz){
            int pos = cnt + __popc(m & ((1u << lane) - 1u));
            float d = (z == 0) ? rowsum[b*N_ + j] : colsum[b*N_ + j];
            float dinv = (d == 0.f) ? 0.f : 1.0f/d;
            eidx[base + pos] = j;
            eval[base + pos] = v*dinv;
        }
        cnt += __popc(m);
    }
    if (lane == 0) ecnt[gw] = cnt;
}

// ---------------------------------------------------------------- cell kernels
// concat: XM[row, c] = c<xC ? x : h (optionally * r-gate); only columns >= cStart
__global__ void k_concat(const float* __restrict__ xsrc, int xC, int isEnc, int t,
                         const float* __restrict__ h, const float* __restrict__ rg,
                         float* __restrict__ XM, int ld, int cStart){
    int C = xC + 128;
    int W = C - cStart;
    int idx = blockIdx.x*256 + threadIdx.x;
    if (idx < NB*W){
        int row = idx / W, c = cStart + idx % W;
        float v;
        if (c < xC){
            if (isEnc){
                int b = row / N_, n = row % N_;
                v = xsrc[(((size_t)b*T_ + t)*N_ + n)*2 + c];
            } else {
                v = xsrc[(size_t)row*xC + c];
            }
        } else {
            int hc = c - xC;
            v = h[(size_t)row*128 + hc];
            if (rg) v *= rg[(size_t)row*256 + hc];
        }
        XM[(size_t)row*ld + c] = v;
    }
}

// Sparse Chebyshev step, both supports in one launch (grid.z = 2):
// out[row, outOff_z + c] = alpha * sum_k val * XM[b, idx, inOff_z + c]
//                          + beta * XM[row, 0 + c]      (betaOff = slot 0)
__global__ void k_spmm(const int* __restrict__ eidx, const float* __restrict__ eval,
                       const int* __restrict__ ecnt,
                       float* __restrict__ XM, int ld,
                       int inOff0, int inOff1, int outOff0, int outOff1,
                       int colStart, int C, float alpha, float beta){
    int z = blockIdx.z;
    int row = blockIdx.y;
    int b = row / N_;
    int gw = z*NB + row;
    __shared__ int   sidx[200];
    __shared__ float sval[200];
    int cnt = ecnt[gw];
    int tid = threadIdx.x;       // 256
    if (tid < cnt){
        sidx[tid] = eidx[(size_t)gw*N_ + tid];
        sval[tid] = eval[(size_t)gw*N_ + tid];
    }
    __syncthreads();
    int c = colStart + tid;
    if (c < C){
        int inOff  = z ? inOff1  : inOff0;
        int outOff = z ? outOff1 : outOff0;
        size_t bb = (size_t)b*N_;
        float acc = 0.f;
        #pragma unroll 4
        for (int k = 0; k < cnt; k++)
            acc += sval[k]*XM[(bb + sidx[k])*ld + inOff + c];
        float v = alpha*acc;
        if (beta != 0.f) v += beta*XM[(size_t)row*ld + c];
        XM[(size_t)row*ld + outOff + c] = v;
    }
}

// GEMM: C[rows, Nout] = A[rows, K] @ B[K, Nout] (+bias), fused epilogues
// 128x64 tile, 256 threads, 8x4 per thread
// mode 0: plain;  mode 1: sigmoid -> G;  mode 2: tanh + GRU update (h in-place)
__global__ void k_gemm(const float* __restrict__ A, int lda,
                       const float* __restrict__ Bm,
                       const float* __restrict__ bias,
                       float* __restrict__ Cout,
                       int K, int Nout, int mode,
                       const float* __restrict__ G,
                       const float* __restrict__ h,
                       float* __restrict__ hout2){
    __shared__ float As[16][128];
    __shared__ float Bs[16][68];
    int tid = threadIdx.y*16 + threadIdx.x;   // (16,16)
    int i0 = blockIdx.y*128, j0 = blockIdx.x*64;
    int rr0 = (tid >> 4) << 3;    // ty*8
    int cc0 = (tid & 15) << 2;    // tx*4
    float acc[8][4];
    #pragma unroll
    for (int r = 0; r < 8; r++)
        #pragma unroll
        for (int s = 0; s < 4; s++) acc[r][s] = 0.f;

    for (int kt = 0; kt < K; kt += 16){
        #pragma unroll
        for (int e = 0; e < 8; e++){
            int idx = e*256 + tid;
            int i = idx >> 4, kk = idx & 15;
            As[kk][i] = (kt+kk < K) ? A[(size_t)(i0+i)*lda + kt+kk] : 0.f;
        }
        #pragma unroll
        for (int e = 0; e < 4; e++){
            int idx = e*256 + tid;
            int kk = idx >> 6, j = idx & 63;
            Bs[kk][j] = (kt+kk < K) ? Bm[(size_t)(kt+kk)*Nout + j0 + j] : 0.f;
        }
        __syncthreads();
        #pragma unroll
        for (int kk = 0; kk < 16; kk++){
            float4 bv = *reinterpret_cast<const float4*>(&Bs[kk][cc0]);
            float4 a0 = *reinterpret_cast<const float4*>(&As[kk][rr0]);
            float4 a1 = *reinterpret_cast<const float4*>(&As[kk][rr0+4]);
            float av[8] = {a0.x,a0.y,a0.z,a0.w,a1.x,a1.y,a1.z,a1.w};
            float bb[4] = {bv.x,bv.y,bv.z,bv.w};
            #pragma unroll
            for (int r = 0; r < 8; r++)
                #pragma unroll
                for (int s = 0; s < 4; s++) acc[r][s] += av[r]*bb[s];
        }
        __syncthreads();
    }
    #pragma unroll
    for (int r = 0; r < 8; r++){
        int row = i0 + rr0 + r;
        #pragma unroll
        for (int s = 0; s < 4; s++){
            int col = j0 + cc0 + s;
            float v = acc[r][s] + (bias ? bias[col] : 0.f);
            if (mode == 0){
                Cout[(size_t)row*Nout + col] = v;
            } else if (mode == 1){
                Cout[(size_t)row*Nout + col] = sigmf_(v);
            } else {
                float c = tanhf(v);
                float u = G[(size_t)row*256 + 128 + col];
                float hn = u*h[(size_t)row*128 + col] + (1.0f - u)*c;
                Cout[(size_t)row*128 + col] = hn;
                if (hout2) hout2[(size_t)row*128 + col] = hn;
            }
        }
    }
}

// proj: out[t,b,n] = h1[row]·projW + projb; also next decoder input
__global__ void k_proj(const float* __restrict__ h1, const float* __restrict__ projW,
                       const float* __restrict__ projb, float* __restrict__ out,
                       float* __restrict__ xdec, int t){
    int row = blockIdx.x; int tid = threadIdx.x;   // 128
    __shared__ float red[128];
    red[tid] = h1[(size_t)row*128 + tid]*projW[tid];
    __syncthreads();
    for (int off = 64; off > 0; off >>= 1){
        if (tid < off) red[tid] += red[tid+off];
        __syncthreads();
    }
    if (tid == 0){
        float v = red[0] + projb[0];
        int b = row / N_, n = row % N_;
        out[((size_t)t*B_ + b)*N_ + n] = v;
        xdec[row] = v;
    }
}

// ---------------------------------------------------------------- host
extern "C" void kernel_launch(void* const* d_in, const int* in_sizes, int n_in,
                              void* d_out, int out_size){
    (void)in_sizes; (void)n_in; (void)out_size;
    float* base = nullptr;
    cudaGetSymbolAddress((void**)&base, g_buf);
    int*   eidx = nullptr; float* evalp = nullptr; int* ecnt = nullptr;
    cudaGetSymbolAddress((void**)&eidx,  g_eidx);
    cudaGetSymbolAddress((void**)&evalp, g_eval);
    cudaGetSymbolAddress((void**)&ecnt,  g_ecnt);

    float* outs   = base + OFF_OUTS;
    float* cur    = base + OFF_CUR;
    float* XM     = base + OFF_XM;
    float* G      = base + OFF_G;
    float* h0     = base + OFF_H0;
    float* h1     = base + OFF_H1;
    float* attn   = base + OFF_ATTN;
    float* adj    = base + OFF_ADJ;
    float* rowsum = base + OFF_RS;
    float* colsum = base + OFF_CS;
    float* pooled = base + OFF_POOL;
    float* keym   = base + OFF_KEYM;
    float* qm     = base + OFF_QM;
    float* qmT    = base + OFF_QMT;
    float* logits = base + OFF_LOG;
    float* xdec   = base + OFF_XDEC;
    float* whhT   = base + OFF_WHHT;
    float* attWT  = base + OFF_ATTWT;
    float* Wp     = base + OFF_WP;

    const float* ein     = (const float*)d_in[0];
    const float* gru_Wih = (const float*)d_in[2];
    const float* gru_Whh = (const float*)d_in[3];
    const float* gru_bih = (const float*)d_in[4];
    const float* gru_bhh = (const float*)d_in[5];
    const float* att_W   = (const float*)d_in[6];
    const float* att_b   = (const float*)d_in[7];
    const float* w_len_C = (const float*)d_in[8];
    const float* w_key   = (const float*)d_in[9];
    const float* w_query = (const float*)d_in[10];
    const float* enc_Wg0 = (const float*)d_in[11];
    const float* enc_bg0 = (const float*)d_in[12];
    const float* enc_Wc0 = (const float*)d_in[13];
    const float* enc_bc0 = (const float*)d_in[14];
    const float* enc_Wg1 = (const float*)d_in[15];
    const float* enc_bg1 = (const float*)d_in[16];
    const float* enc_Wc1 = (const float*)d_in[17];
    const float* enc_bc1 = (const float*)d_in[18];
    const float* dec_Wg0 = (const float*)d_in[19];
    const float* dec_bg0 = (const float*)d_in[20];
    const float* dec_Wc0 = (const float*)d_in[21];
    const float* dec_bc0 = (const float*)d_in[22];
    const float* dec_Wg1 = (const float*)d_in[23];
    const float* dec_bg1 = (const float*)d_in[24];
    const float* dec_Wc1 = (const float*)d_in[25];
    const float* dec_bc1 = (const float*)d_in[26];
    const float* proj_W  = (const float*)d_in[27];
    const float* proj_b  = (const float*)d_in[28];
    const int*   topk    = (const int*)d_in[29];
    float* out = (float*)d_out;

    dim3 gblk(16,16);

    // ---- prep: transposes & weight reorders
    k_transpose<<<(384*128+255)/256,256>>>(gru_Whh, whhT, 384, 128);
    k_transpose<<<(64*128+255)/256,256>>>(att_W, attWT, 64, 128);
    struct RW { const float* W; int off; int C; int Nout; };
    RW rws[8] = {
        {enc_Wg0, WPO_EG0, 130, 256}, {enc_Wc0, WPO_EC0, 130, 128},
        {enc_Wg1, WPO_EG1, 256, 256}, {enc_Wc1, WPO_EC1, 256, 128},
        {dec_Wg0, WPO_DG0, 129, 256}, {dec_Wc0, WPO_DC0, 129, 128},
        {dec_Wg1, WPO_DG1, 256, 256}, {dec_Wc1, WPO_DC1, 256, 128},
    };
    for (int i = 0; i < 8; i++){
        int tot = rws[i].C*5*rws[i].Nout;
        k_reorder<<<(tot+255)/256,256>>>(rws[i].W, Wp + rws[i].off, rws[i].C, rws[i].Nout);
    }

    // ---- zero initial states
    k_zero<<<(NB*128+255)/256,256>>>(h0, NB*128);
    k_zero<<<(NB*128+255)/256,256>>>(h1, NB*128);
    k_zero<<<(NB+255)/256,256>>>(xdec, NB);

    // ---- supports
    k_gru<<<NB/8,128>>>(ein, gru_Wih, whhT, gru_bih, gru_bhh, outs);
    k_attlogits<<<NB,64>>>(outs, attWT, att_b, w_len_C, logits);
    k_pool<<<NB,128>>>(outs, logits, pooled);
    k_gemm<<<dim3(1,50),gblk>>>(pooled,128, w_key,   nullptr, keym, 128, 64, 0, nullptr, nullptr, nullptr);
    k_gemm<<<dim3(1,50),gblk>>>(pooled,128, w_query, nullptr, qm,   128, 64, 0, nullptr, nullptr, nullptr);
    k_qmT<<<(B_*N_*64+255)/256,256>>>(qm, qmT);
    k_attn<<<NB,256>>>(keym, qmT, attn);
    k_topk<<<NB,256>>>(attn, adj, rowsum, topk);
    k_colsum<<<B_,256>>>(adj, colsum);
    k_ell<<<(2*NB*32)/256,256>>>(adj, rowsum, colsum, eidx, evalp, ecnt);

    // ---- one DCGRU cell
    auto cell = [&](const float* xsrc, int xC, int isEnc, int t, float* h,
                    const float* Wg, const float* bg,
                    const float* Wc, const float* bc, float* hout2){
        int C = xC + 128, ld = 5*C, K = 5*C;
        dim3 sgrd(1, NB, 2);
        // gate gconv (all columns)
        k_concat<<<(NB*C+255)/256,256>>>(xsrc, xC, isEnc, t, h, nullptr, XM, ld, 0);
        k_spmm<<<sgrd,256>>>(eidx, evalp, ecnt, XM, ld, 0,   0,   C,   3*C, 0, C, 1.f,  0.f);
        k_spmm<<<sgrd,256>>>(eidx, evalp, ecnt, XM, ld, C,   3*C, 2*C, 4*C, 0, C, 2.f, -1.f);
        k_gemm<<<dim3(4,50),gblk>>>(XM, ld, Wg, bg, G, K, 256, 1, nullptr, nullptr, nullptr);
        // candidate gconv — only h-columns change (operator is column-separable)
        k_concat<<<(NB*128+255)/256,256>>>(xsrc, xC, isEnc, t, h, G, XM, ld, xC);
        k_spmm<<<sgrd,256>>>(eidx, evalp, ecnt, XM, ld, 0,   0,   C,   3*C, xC, C, 1.f,  0.f);
        k_spmm<<<sgrd,256>>>(eidx, evalp, ecnt, XM, ld, C,   3*C, 2*C, 4*C, xC, C, 2.f, -1.f);
        k_gemm<<<dim3(2,50),gblk>>>(XM, ld, Wc, bc, h, K, 128, 2, G, h, hout2);
    };

    // ---- encoder
    for (int t = 0; t < T_; t++)
        cell(ein, 2, 1, t, h0, Wp+WPO_EG0, enc_bg0, Wp+WPO_EC0, enc_bc0,
             cur + (size_t)t*NB*128);
    for (int t = 0; t < T_; t++)
        cell(cur + (size_t)t*NB*128, 128, 0, 0, h1, Wp+WPO_EG1, enc_bg1,
             Wp+WPO_EC1, enc_bc1, nullptr);

    // ---- decoder (autoregressive)
    for (int t = 0; t < T_; t++){
        cell(xdec, 1, 0, 0, h0, Wp+WPO_DG0, dec_bg0, Wp+WPO_DC0, dec_bc0, nullptr);
        cell(h0, 128, 0, 0, h1, Wp+WPO_DG1, dec_bg1, Wp+WPO_DC1, dec_bc1, nullptr);
        k_proj<<<NB,128>>>(h1, proj_W, proj_b, out, xdec, t);
    }
}

// round 17
// speedup vs baseline: 1.8464x; 1.0001x over previous
#include <cuda_runtime.h>
#include <math.h>

// ---------------------------------------------------------------- constants
#define B_    32
#define T_    12
#define N_    200
#define H_    128
#define NB    6400            // B_*N_
#define NN    40000           // N_*N_
#define INV_SQRT_H 0.08838834764831845f   // 1/sqrt(128)

static __device__ __forceinline__ float sigmf_(float x){ return 1.0f/(1.0f+expf(-x)); }

// ---------------------------------------------------------------- scratch
#define OFF_OUTS   0ULL                      // 12*6400*128
#define OFF_CUR    9830400ULL                // 12*6400*128
#define OFF_XM     19660800ULL               // 6400*1280
#define OFF_G      27852800ULL               // 6400*256
#define OFF_H0     29491200ULL               // 6400*128
#define OFF_H1     30310400ULL               // 6400*128
#define OFF_ATTN   31129600ULL               // 32*40000
#define OFF_ADJ    32409600ULL               // 32*40000
#define OFF_RS     36249600ULL               // 6400
#define OFF_CS     36256000ULL               // 6400
#define OFF_POOL   36262400ULL               // 6400*128
#define OFF_KEYM   37081600ULL               // 6400*64
#define OFF_QM     37491200ULL               // 6400*64
#define OFF_QMT    37900800ULL               // 32*64*200
#define OFF_LOG    38310400ULL               // 12*6400
#define OFF_XDEC   38387200ULL               // 6400
#define OFF_WHHT   38393600ULL               // 128*384
#define OFF_ATTWT  38442752ULL               // 128*64
#define OFF_WP     38450944ULL               // 1480320
#define TOTAL_F    39931264ULL

__device__ float g_buf[TOTAL_F];

// ELL sparse supports: z in {0:s1, 1:s2}, per row up to N_ entries
__device__ int   g_eidx[2*NB*N_];
__device__ float g_eval[2*NB*N_];
__device__ int   g_ecnt[2*NB];

// Wp sub-offsets (floats, relative to OFF_WP)
#define WPO_EG0 0
#define WPO_EC0 166400
#define WPO_EG1 249600
#define WPO_EC1 577280
#define WPO_DG0 741120
#define WPO_DC0 906240
#define WPO_DG1 988800
#define WPO_DC1 1316480

// ---------------------------------------------------------------- utility
__global__ void k_zero(float* p, int n){
    int i = blockIdx.x*256 + threadIdx.x;
    if (i < n) p[i] = 0.0f;
}

__global__ void k_transpose(const float* __restrict__ A, float* __restrict__ AT, int R, int C){
    int i = blockIdx.x*256 + threadIdx.x;
    if (i < R*C){ int r = i / C, c = i % C; AT[(size_t)c*R + r] = A[i]; }
}

// Wp[(m*C+c)*Nout + o] = W[(c*5+m)*Nout + o]
__global__ void k_reorder(const float* __restrict__ W, float* __restrict__ Wp, int C, int Nout){
    int i = blockIdx.x*256 + threadIdx.x;
    int tot = C*5*Nout;
    if (i < tot){
        int o = i % Nout; int rest = i / Nout;
        int m = rest / C; int c = rest % C;
        Wp[i] = W[((size_t)c*5 + m)*Nout + o];
    }
}

__global__ void k_qmT(const float* __restrict__ qm, float* __restrict__ qmT){
    int i = blockIdx.x*256 + threadIdx.x;
    if (i < B_*N_*64){
        int d = i % 64; int rest = i / 64; int m = rest % N_, b = rest / N_;
        qmT[((size_t)b*64 + d)*N_ + m] = qm[i];
    }
}

// ---------------------------------------------------------------- GRU (supports)
__global__ void k_gru(const float* __restrict__ ein, const float* __restrict__ Wih,
                      const float* __restrict__ WhhT, const float* __restrict__ bih,
                      const float* __restrict__ bhh, float* __restrict__ outs){
    int tid = threadIdx.x;           // 128
    int r0  = blockIdx.x * 8;
    __shared__ float hs[8][128];
    #pragma unroll
    for (int rr = 0; rr < 8; rr++) hs[rr][tid] = 0.0f;

    float wi00 = Wih[tid*2],         wi01 = Wih[tid*2+1];
    float wi10 = Wih[(128+tid)*2],   wi11 = Wih[(128+tid)*2+1];
    float wi20 = Wih[(256+tid)*2],   wi21 = Wih[(256+tid)*2+1];
    float bi0 = bih[tid], bi1 = bih[128+tid], bi2 = bih[256+tid];
    float bh0 = bhh[tid], bh1 = bhh[128+tid], bh2 = bhh[256+tid];
    __syncthreads();

    for (int t = 0; t < T_; t++){
        float a0[8], a1[8], a2[8];
        #pragma unroll
        for (int rr = 0; rr < 8; rr++){ a0[rr]=0.f; a1[rr]=0.f; a2[rr]=0.f; }
        for (int k = 0; k < 128; k++){
            float w0 = WhhT[k*384 + tid];
            float w1 = WhhT[k*384 + 128 + tid];
            float w2 = WhhT[k*384 + 256 + tid];
            #pragma unroll
            for (int rr = 0; rr < 8; rr++){
                float hk = hs[rr][k];
                a0[rr] += w0*hk; a1[rr] += w1*hk; a2[rr] += w2*hk;
            }
        }
        __syncthreads();
        #pragma unroll
        for (int rr = 0; rr < 8; rr++){
            int row = r0 + rr;
            int b = row & 31, n = row >> 5;      // row = n*B_ + b
            size_t xi = (((size_t)b*T_ + t)*N_ + n)*2;
            float x0 = ein[xi], x1 = ein[xi+1];
            float ir = x0*wi00 + x1*wi01 + bi0;
            float iz = x0*wi10 + x1*wi11 + bi1;
            float ig = x0*wi20 + x1*wi21 + bi2;
            float hprev = hs[rr][tid];
            float rg = sigmf_(ir + a0[rr] + bh0);
            float zg = sigmf_(iz + a1[rr] + bh1);
            float ng = tanhf(ig + rg*(a2[rr] + bh2));
            float hn = (1.0f - zg)*ng + zg*hprev;
            hs[rr][tid] = hn;
            outs[((size_t)t*NB + row)*128 + tid] = hn;
        }
        __syncthreads();
    }
}

__global__ void k_attlogits(const float* __restrict__ outs, const float* __restrict__ attWT,
                            const float* __restrict__ attb, const float* __restrict__ wlen,
                            float* __restrict__ logits){
    int row = blockIdx.x;
    int d = threadIdx.x;             // 64
    __shared__ float ho[128];
    __shared__ float red[64];
    float bd = attb[d], wd = wlen[d];
    for (int t = 0; t < T_; t++){
        ho[d]      = outs[((size_t)t*NB + row)*128 + d];
        ho[d + 64] = outs[((size_t)t*NB + row)*128 + d + 64];
        __syncthreads();
        float acc = 0.f;
        #pragma unroll 4
        for (int hh = 0; hh < 128; hh++) acc += ho[hh]*attWT[hh*64 + d];
        float sc = fmaxf(acc + bd, 0.f) * wd;
        red[d] = sc; __syncthreads();
        for (int off = 32; off > 0; off >>= 1){
            if (d < off) red[d] += red[d + off];
            __syncthreads();
        }
        if (d == 0) logits[t*NB + row] = red[0];
        __syncthreads();
    }
}

__global__ void k_pool(const float* __restrict__ outs, const float* __restrict__ logits,
                       float* __restrict__ pooled){
    int row = blockIdx.x, tid = threadIdx.x;   // 128
    __shared__ float w[12];
    if (tid < 12) w[tid] = logits[tid*NB + row];
    __syncthreads();
    if (tid == 0){
        float mx = w[0];
        for (int t = 1; t < 12; t++) mx = fmaxf(mx, w[t]);
        float s = 0.f;
        for (int t = 0; t < 12; t++){ w[t] = expf(w[t]-mx); s += w[t]; }
        float inv = 1.0f/s;
        for (int t = 0; t < 12; t++) w[t] *= inv;
    }
    __syncthreads();
    float acc = 0.f;
    #pragma unroll
    for (int t = 0; t < 12; t++) acc += w[t]*outs[((size_t)t*NB + row)*128 + tid];
    int b = row & 31, n = row >> 5;
    pooled[((size_t)b*N_ + n)*128 + tid] = acc;
}

__global__ void k_attn(const float* __restrict__ keym, const float* __restrict__ qmT,
                       float* __restrict__ attn){
    int bn = blockIdx.x; int b = bn / N_;
    int tid = threadIdx.x;           // 256
    __shared__ float keys[64];
    __shared__ float vals[256];
    __shared__ float red[256];
    if (tid < 64) keys[tid] = keym[(size_t)bn*64 + tid];
    __syncthreads();
    float v = -1e30f;
    if (tid < N_){
        float acc = 0.f;
        const float* q = qmT + (size_t)b*64*N_;
        #pragma unroll 4
        for (int d = 0; d < 64; d++) acc += keys[d]*q[d*N_ + tid];
        v = acc * INV_SQRT_H;
    }
    vals[tid] = v; red[tid] = v;
    __syncthreads();
    for (int off = 128; off > 0; off >>= 1){
        if (tid < off) red[tid] = fmaxf(red[tid], red[tid+off]);
        __syncthreads();
    }
    float mx = red[0];
    __syncthreads();
    float e = (tid < N_) ? expf(vals[tid]-mx) : 0.f;
    red[tid] = e;
    __syncthreads();
    for (int off = 128; off > 0; off >>= 1){
        if (tid < off) red[tid] += red[tid+off];
        __syncthreads();
    }
    float inv = 1.0f/red[0];
    if (tid < N_) attn[(size_t)b*NN + (bn % N_)*N_ + tid] = e*inv;
}

__global__ void k_topk(const float* __restrict__ attn, float* __restrict__ adj,
                       float* __restrict__ rowsum, const int* __restrict__ topk){
    int bn = blockIdx.x; int b = bn / N_, n = bn % N_;
    int tid = threadIdx.x;           // 256
    __shared__ float vals[200];
    __shared__ float red[256];
    if (tid < N_) vals[tid] = attn[(size_t)b*NN + n*N_ + tid];
    __syncthreads();
    int kk = *topk;
    float cand = -1e30f;
    if (tid < N_){
        float v = vals[tid]; int cnt = 0;
        for (int j = 0; j < N_; j++) cnt += (vals[j] >= v) ? 1 : 0;
        if (cnt >= kk) cand = v;
    }
    red[tid] = cand;
    __syncthreads();
    for (int off = 128; off > 0; off >>= 1){
        if (tid < off) red[tid] = fmaxf(red[tid], red[tid+off]);
        __syncthreads();
    }
    float kth = red[0];
    __syncthreads();
    float a = 0.f;
    if (tid < N_){
        float v = vals[tid];
        a = ((v >= kth) ? v : 0.f) + ((tid == n) ? 1.0f : 0.f);
        adj[(size_t)b*NN + n*N_ + tid] = a;
    }
    red[tid] = (tid < N_) ? a : 0.f;
    __syncthreads();
    for (int off = 128; off > 0; off >>= 1){
        if (tid < off) red[tid] += red[tid+off];
        __syncthreads();
    }
    if (tid == 0) rowsum[bn] = red[0];
}

__global__ void k_colsum(const float* __restrict__ adj, float* __restrict__ colsum){
    int b = blockIdx.x; int m = threadIdx.x;     // 256
    if (m < N_){
        float s = 0.f;
        for (int i = 0; i < N_; i++) s += adj[(size_t)b*NN + i*N_ + m];
        colsum[b*N_ + m] = s;
    }
}

// ---------------------------------------------------------------- ELL build
// s1[b,i,j] = adj[b,j,i]/rowsum[b,j]; s2[b,i,j] = adj[b,i,j]/colsum[b,j]
// One warp per (z,row); ballot-ordered compaction => deterministic order.
__global__ void k_ell(const float* __restrict__ adj, const float* __restrict__ rowsum,
                      const float* __restrict__ colsum,
                      int* __restrict__ eidx, float* __restrict__ eval,
                      int* __restrict__ ecnt){
    int gw = (blockIdx.x*blockDim.x + threadIdx.x) >> 5;
    int lane = threadIdx.x & 31;
    if (gw >= 2*NB) return;
    int z = gw / NB; int row = gw % NB; int b = row / N_, i = row % N_;
    int cnt = 0;
    size_t base = (size_t)gw * N_;
    for (int j0 = 0; j0 < N_; j0 += 32){
        int j = j0 + lane;
        float v = 0.f;
        if (j < N_)
            v = (z == 0) ? adj[(size_t)b*NN + j*N_ + i]
                         : adj[(size_t)b*NN + i*N_ + j];
        bool nz = (v != 0.f);
        unsigned m = __ballot_sync(0xffffffffu, nz);
        if (nz){
            int pos = cnt + __popc(m & ((1u << lane) - 1u));
            float d = (z == 0) ? rowsum[b*N_ + j] : colsum[b*N_ + j];
            float dinv = (d == 0.f) ? 0.f : 1.0f/d;
            eidx[base + pos] = j;
            eval[base + pos] = v*dinv;
        }
        cnt += __popc(m);
    }
    if (lane == 0) ecnt[gw] = cnt;
}

// ---------------------------------------------------------------- cell kernels
// concat: XM[row, c] = c<xC ? x : h (optionally * r-gate); only columns >= cStart
__global__ void k_concat(const float* __restrict__ xsrc, int xC, int isEnc, int t,
                         const float* __restrict__ h, const float* __restrict__ rg,
                         float* __restrict__ XM, int ld, int cStart){
    int C = xC + 128;
    int W = C - cStart;
    int idx = blockIdx.x*256 + threadIdx.x;
    if (idx < NB*W){
        int row = idx / W, c = cStart + idx % W;
        float v;
        if (c < xC){
            if (isEnc){
                int b = row / N_, n = row % N_;
                v = xsrc[(((size_t)b*T_ + t)*N_ + n)*2 + c];
            } else {
                v = xsrc[(size_t)row*xC + c];
            }
        } else {
            int hc = c - xC;
            v = h[(size_t)row*128 + hc];
            if (rg) v *= rg[(size_t)row*256 + hc];
        }
        XM[(size_t)row*ld + c] = v;
    }
}

// Sparse Chebyshev step, both supports in one launch (grid.z = 2):
// out[row, outOff_z + c] = alpha * sum_k val * XM[b, idx, inOff_z + c]
//                          + beta * XM[row, 0 + c]      (betaOff = slot 0)
__global__ void k_spmm(const int* __restrict__ eidx, const float* __restrict__ eval,
                       const int* __restrict__ ecnt,
                       float* __restrict__ XM, int ld,
                       int inOff0, int inOff1, int outOff0, int outOff1,
                       int colStart, int C, float alpha, float beta){
    int z = blockIdx.z;
    int row = blockIdx.y;
    int b = row / N_;
    int gw = z*NB + row;
    __shared__ int   sidx[200];
    __shared__ float sval[200];
    int cnt = ecnt[gw];
    int tid = threadIdx.x;       // 256
    if (tid < cnt){
        sidx[tid] = eidx[(size_t)gw*N_ + tid];
        sval[tid] = eval[(size_t)gw*N_ + tid];
    }
    __syncthreads();
    int c = colStart + tid;
    if (c < C){
        int inOff  = z ? inOff1  : inOff0;
        int outOff = z ? outOff1 : outOff0;
        size_t bb = (size_t)b*N_;
        float acc = 0.f;
        #pragma unroll 4
        for (int k = 0; k < cnt; k++)
            acc += sval[k]*XM[(bb + sidx[k])*ld + inOff + c];
        float v = alpha*acc;
        if (beta != 0.f) v += beta*XM[(size_t)row*ld + c];
        XM[(size_t)row*ld + outOff + c] = v;
    }
}

// GEMM: C[rows, Nout] = A[rows, K] @ B[K, Nout] (+bias), fused epilogues
// 128x64 tile, 256 threads, 8x4 per thread
// mode 0: plain;  mode 1: sigmoid -> G;  mode 2: tanh + GRU update (h in-place)
__global__ void k_gemm(const float* __restrict__ A, int lda,
                       const float* __restrict__ Bm,
                       const float* __restrict__ bias,
                       float* __restrict__ Cout,
                       int K, int Nout, int mode,
                       const float* __restrict__ G,
                       const float* __restrict__ h,
                       float* __restrict__ hout2){
    __shared__ float As[16][128];
    __shared__ float Bs[16][68];
    int tid = threadIdx.y*16 + threadIdx.x;   // (16,16)
    int i0 = blockIdx.y*128, j0 = blockIdx.x*64;
    int rr0 = (tid >> 4) << 3;    // ty*8
    int cc0 = (tid & 15) << 2;    // tx*4
    float acc[8][4];
    #pragma unroll
    for (int r = 0; r < 8; r++)
        #pragma unroll
        for (int s = 0; s < 4; s++) acc[r][s] = 0.f;

    for (int kt = 0; kt < K; kt += 16){
        #pragma unroll
        for (int e = 0; e < 8; e++){
            int idx = e*256 + tid;
            int i = idx >> 4, kk = idx & 15;
            As[kk][i] = (kt+kk < K) ? A[(size_t)(i0+i)*lda + kt+kk] : 0.f;
        }
        #pragma unroll
        for (int e = 0; e < 4; e++){
            int idx = e*256 + tid;
            int kk = idx >> 6, j = idx & 63;
            Bs[kk][j] = (kt+kk < K) ? Bm[(size_t)(kt+kk)*Nout + j0 + j] : 0.f;
        }
        __syncthreads();
        #pragma unroll
        for (int kk = 0; kk < 16; kk++){
            float4 bv = *reinterpret_cast<const float4*>(&Bs[kk][cc0]);
            float4 a0 = *reinterpret_cast<const float4*>(&As[kk][rr0]);
            float4 a1 = *reinterpret_cast<const float4*>(&As[kk][rr0+4]);
            float av[8] = {a0.x,a0.y,a0.z,a0.w,a1.x,a1.y,a1.z,a1.w};
            float bb[4] = {bv.x,bv.y,bv.z,bv.w};
            #pragma unroll
            for (int r = 0; r < 8; r++)
                #pragma unroll
                for (int s = 0; s < 4; s++) acc[r][s] += av[r]*bb[s];
        }
        __syncthreads();
    }
    #pragma unroll
    for (int r = 0; r < 8; r++){
        int row = i0 + rr0 + r;
        #pragma unroll
        for (int s = 0; s < 4; s++){
            int col = j0 + cc0 + s;
            float v = acc[r][s] + (bias ? bias[col] : 0.f);
            if (mode == 0){
                Cout[(size_t)row*Nout + col] = v;
            } else if (mode == 1){
                Cout[(size_t)row*Nout + col] = sigmf_(v);
            } else {
                float c = tanhf(v);
                float u = G[(size_t)row*256 + 128 + col];
                float hn = u*h[(size_t)row*128 + col] + (1.0f - u)*c;
                Cout[(size_t)row*128 + col] = hn;
                if (hout2) hout2[(size_t)row*128 + col] = hn;
            }
        }
    }
}

// proj: out[t,b,n] = h1[row]·projW + projb; also next decoder input
__global__ void k_proj(const float* __restrict__ h1, const float* __restrict__ projW,
                       const float* __restrict__ projb, float* __restrict__ out,
                       float* __restrict__ xdec, int t){
    int row = blockIdx.x; int tid = threadIdx.x;   // 128
    __shared__ float red[128];
    red[tid] = h1[(size_t)row*128 + tid]*projW[tid];
    __syncthreads();
    for (int off = 64; off > 0; off >>= 1){
        if (tid < off) red[tid] += red[tid+off];
        __syncthreads();
    }
    if (tid == 0){
        float v = red[0] + projb[0];
        int b = row / N_, n = row % N_;
        out[((size_t)t*B_ + b)*N_ + n] = v;
        xdec[row] = v;
    }
}

// ---------------------------------------------------------------- host
extern "C" void kernel_launch(void* const* d_in, const int* in_sizes, int n_in,
                              void* d_out, int out_size){
    (void)in_sizes; (void)n_in; (void)out_size;
    float* base = nullptr;
    cudaGetSymbolAddress((void**)&base, g_buf);
    int*   eidx = nullptr; float* evalp = nullptr; int* ecnt = nullptr;
    cudaGetSymbolAddress((void**)&eidx,  g_eidx);
    cudaGetSymbolAddress((void**)&evalp, g_eval);
    cudaGetSymbolAddress((void**)&ecnt,  g_ecnt);

    float* outs   = base + OFF_OUTS;
    float* cur    = base + OFF_CUR;
    float* XM     = base + OFF_XM;
    float* G      = base + OFF_G;
    float* h0     = base + OFF_H0;
    float* h1     = base + OFF_H1;
    float* attn   = base + OFF_ATTN;
    float* adj    = base + OFF_ADJ;
    float* rowsum = base + OFF_RS;
    float* colsum = base + OFF_CS;
    float* pooled = base + OFF_POOL;
    float* keym   = base + OFF_KEYM;
    float* qm     = base + OFF_QM;
    float* qmT    = base + OFF_QMT;
    float* logits = base + OFF_LOG;
    float* xdec   = base + OFF_XDEC;
    float* whhT   = base + OFF_WHHT;
    float* attWT  = base + OFF_ATTWT;
    float* Wp     = base + OFF_WP;

    const float* ein     = (const float*)d_in[0];
    const float* gru_Wih = (const float*)d_in[2];
    const float* gru_Whh = (const float*)d_in[3];
    const float* gru_bih = (const float*)d_in[4];
    const float* gru_bhh = (const float*)d_in[5];
    const float* att_W   = (const float*)d_in[6];
    const float* att_b   = (const float*)d_in[7];
    const float* w_len_C = (const float*)d_in[8];
    const float* w_key   = (const float*)d_in[9];
    const float* w_query = (const float*)d_in[10];
    const float* enc_Wg0 = (const float*)d_in[11];
    const float* enc_bg0 = (const float*)d_in[12];
    const float* enc_Wc0 = (const float*)d_in[13];
    const float* enc_bc0 = (const float*)d_in[14];
    const float* enc_Wg1 = (const float*)d_in[15];
    const float* enc_bg1 = (const float*)d_in[16];
    const float* enc_Wc1 = (const float*)d_in[17];
    const float* enc_bc1 = (const float*)d_in[18];
    const float* dec_Wg0 = (const float*)d_in[19];
    const float* dec_bg0 = (const float*)d_in[20];
    const float* dec_Wc0 = (const float*)d_in[21];
    const float* dec_bc0 = (const float*)d_in[22];
    const float* dec_Wg1 = (const float*)d_in[23];
    const float* dec_bg1 = (const float*)d_in[24];
    const float* dec_Wc1 = (const float*)d_in[25];
    const float* dec_bc1 = (const float*)d_in[26];
    const float* proj_W  = (const float*)d_in[27];
    const float* proj_b  = (const float*)d_in[28];
    const int*   topk    = (const int*)d_in[29];
    float* out = (float*)d_out;

    dim3 gblk(16,16);

    // ---- prep: transposes & weight reorders
    k_transpose<<<(384*128+255)/256,256>>>(gru_Whh, whhT, 384, 128);
    k_transpose<<<(64*128+255)/256,256>>>(att_W, attWT, 64, 128);
    struct RW { const float* W; int off; int C; int Nout; };
    RW rws[8] = {
        {enc_Wg0, WPO_EG0, 130, 256}, {enc_Wc0, WPO_EC0, 130, 128},
        {enc_Wg1, WPO_EG1, 256, 256}, {enc_Wc1, WPO_EC1, 256, 128},
        {dec_Wg0, WPO_DG0, 129, 256}, {dec_Wc0, WPO_DC0, 129, 128},
        {dec_Wg1, WPO_DG1, 256, 256}, {dec_Wc1, WPO_DC1, 256, 128},
    };
    for (int i = 0; i < 8; i++){
        int tot = rws[i].C*5*rws[i].Nout;
        k_reorder<<<(tot+255)/256,256>>>(rws[i].W, Wp + rws[i].off, rws[i].C, rws[i].Nout);
    }

    // ---- zero initial states
    k_zero<<<(NB*128+255)/256,256>>>(h0, NB*128);
    k_zero<<<(NB*128+255)/256,256>>>(h1, NB*128);
    k_zero<<<(NB+255)/256,256>>>(xdec, NB);

    // ---- supports
    k_gru<<<NB/8,128>>>(ein, gru_Wih, whhT, gru_bih, gru_bhh, outs);
    k_attlogits<<<NB,64>>>(outs, attWT, att_b, w_len_C, logits);
    k_pool<<<NB,128>>>(outs, logits, pooled);
    k_gemm<<<dim3(1,50),gblk>>>(pooled,128, w_key,   nullptr, keym, 128, 64, 0, nullptr, nullptr, nullptr);
    k_gemm<<<dim3(1,50),gblk>>>(pooled,128, w_query, nullptr, qm,   128, 64, 0, nullptr, nullptr, nullptr);
    k_qmT<<<(B_*N_*64+255)/256,256>>>(qm, qmT);
    k_attn<<<NB,256>>>(keym, qmT, attn);
    k_topk<<<NB,256>>>(attn, adj, rowsum, topk);
    k_colsum<<<B_,256>>>(adj, colsum);
    k_ell<<<(2*NB*32)/256,256>>>(adj, rowsum, colsum, eidx, evalp, ecnt);

    // ---- one DCGRU cell
    auto cell = [&](const float* xsrc, int xC, int isEnc, int t, float* h,
                    const float* Wg, const float* bg,
                    const float* Wc, const float* bc, float* hout2){
        int C = xC + 128, ld = 5*C, K = 5*C;
        dim3 sgrd(1, NB, 2);
        // gate gconv (all columns)
        k_concat<<<(NB*C+255)/256,256>>>(xsrc, xC, isEnc, t, h, nullptr, XM, ld, 0);
        k_spmm<<<sgrd,256>>>(eidx, evalp, ecnt, XM, ld, 0,   0,   C,   3*C, 0, C, 1.f,  0.f);
        k_spmm<<<sgrd,256>>>(eidx, evalp, ecnt, XM, ld, C,   3*C, 2*C, 4*C, 0, C, 2.f, -1.f);
        k_gemm<<<dim3(4,50),gblk>>>(XM, ld, Wg, bg, G, K, 256, 1, nullptr, nullptr, nullptr);
        // candidate gconv — only h-columns change (operator is column-separable)
        k_concat<<<(NB*128+255)/256,256>>>(xsrc, xC, isEnc, t, h, G, XM, ld, xC);
        k_spmm<<<sgrd,256>>>(eidx, evalp, ecnt, XM, ld, 0,   0,   C,   3*C, xC, C, 1.f,  0.f);
        k_spmm<<<sgrd,256>>>(eidx, evalp, ecnt, XM, ld, C,   3*C, 2*C, 4*C, xC, C, 2.f, -1.f);
        k_gemm<<<dim3(2,50),gblk>>>(XM, ld, Wc, bc, h, K, 128, 2, G, h, hout2);
    };

    // ---- encoder
    for (int t = 0; t < T_; t++)
        cell(ein, 2, 1, t, h0, Wp+WPO_EG0, enc_bg0, Wp+WPO_EC0, enc_bc0,
             cur + (size_t)t*NB*128);
    for (int t = 0; t < T_; t++)
        cell(cur + (size_t)t*NB*128, 128, 0, 0, h1, Wp+WPO_EG1, enc_bg1,
             Wp+WPO_EC1, enc_bc1, nullptr);

    // ---- decoder (autoregressive)
    for (int t = 0; t < T_; t++){
        cell(xdec, 1, 0, 0, h0, Wp+WPO_DG0, dec_bg0, Wp+WPO_DC0, dec_bc0, nullptr);
        cell(h0, 128, 0, 0, h1, Wp+WPO_DG1, dec_bg1, Wp+WPO_DC1, dec_bc1, nullptr);
        k_proj<<<NB,128>>>(h1, proj_W, proj_b, out, xdec, t);
    }
}